// round 8
// baseline (speedup 1.0000x reference)
#include <cuda_runtime.h>
#include <cstdint>

// Problem constants
#define T_STEPS 512
#define BATCH   256
#define INPUT_  256
#define HID_    64
#define GATES_  256            // 4*HID
#define OUT_    1024
#define M_ROWS  (T_STEPS * BATCH)          // 131072
#define OUT_ELEMS ((size_t)M_ROWS * OUT_)  // 134217728
#define HC_ELEMS  (BATCH * HID_)           // 16384

// Scratch (allocation-free rule: __device__ globals)
__device__ float g_xg[(size_t)M_ROWS * GATES_];  // 134 MB: x @ W_ih^T + (b_ih+b_hh)
__device__ float g_hs[(size_t)M_ROWS * HID_];    // 33.5 MB: per-step hidden states

// ---------- f32x2 packed-FMA helpers (full-rate fp32 on sm_103a) ----------
__device__ __forceinline__ unsigned long long pk(float x, float y) {
    unsigned long long r;
    asm("mov.b64 %0, {%1, %2};" : "=l"(r) : "f"(x), "f"(y));
    return r;
}
__device__ __forceinline__ void fma2(unsigned long long& d,
                                     unsigned long long a,
                                     unsigned long long b) {
    asm("fma.rn.f32x2 %0, %1, %2, %0;" : "+l"(d) : "l"(a), "l"(b));
}
__device__ __forceinline__ float2 upk(unsigned long long v) {
    float2 r;
    asm("mov.b64 {%0, %1}, %2;" : "=f"(r.x), "=f"(r.y) : "l"(v));
    return r;
}
__device__ __forceinline__ float sigm(float x) {
    return 1.0f / (1.0f + __expf(-x));
}

// ---------- Generic fp32 GEMM: C[m][n] = act( A[m][K]·B[n][K] + bias ) ----------
// Block tile 128x128, micro tile 8x8, BK=32 staged through smem.
// K is packed in pairs: accumulator lanes hold even-k / odd-k partial sums.
template <int K, int N, bool SIG>
__device__ __forceinline__ void gemm_body(const float* __restrict__ A,
                                          const float* __restrict__ B,
                                          const float* __restrict__ b1,
                                          const float* __restrict__ b2,
                                          float* __restrict__ C) {
    constexpr int LD = 130;  // float2 units per k2-row (pad vs 128 to break conflicts)
    __shared__ unsigned long long As[16 * LD];  // [k2][m]      (m contiguous)
    __shared__ unsigned long long Bs[16 * LD];  // [k2][p(n)]   p(n)=(n&7)*16 + n>>3

    const int tid = threadIdx.x;
    const int tx = tid & 15;        // n-group: cols n0 + 8*tx + j
    const int ty = tid >> 4;        // m-group: rows m0 + 8*ty + i
    const int m0 = blockIdx.y * 128;
    const int n0 = blockIdx.x * 128;

    unsigned long long acc[8][8];
#pragma unroll
    for (int i = 0; i < 8; i++)
#pragma unroll
        for (int j = 0; j < 8; j++) acc[i][j] = 0ull;

    const int r  = tid >> 3;  // 0..31 row within load pass
    const int c4 = tid & 7;   // 0..7  float4 index along k

    for (int kt = 0; kt < K; kt += 32) {
        // Load 128x32 tiles of A and B, pair-transposed into smem
#pragma unroll
        for (int p = 0; p < 4; p++) {
            int row = r + p * 32;
            float4 va = *(const float4*)(A + (size_t)(m0 + row) * K + kt + c4 * 4);
            As[(2 * c4) * LD + row]     = pk(va.x, va.y);
            As[(2 * c4 + 1) * LD + row] = pk(va.z, va.w);
            float4 vb = *(const float4*)(B + (size_t)(n0 + row) * K + kt + c4 * 4);
            int pn = ((row & 7) << 4) + (row >> 3);
            Bs[(2 * c4) * LD + pn]     = pk(vb.x, vb.y);
            Bs[(2 * c4 + 1) * LD + pn] = pk(vb.z, vb.w);
        }
        __syncthreads();

#pragma unroll
        for (int k2 = 0; k2 < 16; k2++) {
            unsigned long long au[8], bu[8];
            const ulonglong2* ap = (const ulonglong2*)(As + k2 * LD + ty * 8);
#pragma unroll
            for (int q = 0; q < 4; q++) {
                ulonglong2 t2 = ap[q];
                au[2 * q]     = t2.x;
                au[2 * q + 1] = t2.y;
            }
#pragma unroll
            for (int j = 0; j < 8; j++) bu[j] = Bs[k2 * LD + j * 16 + tx];
#pragma unroll
            for (int i = 0; i < 8; i++)
#pragma unroll
                for (int j = 0; j < 8; j++) fma2(acc[i][j], au[i], bu[j]);
        }
        __syncthreads();
    }

    // Epilogue: reduce even/odd-k lanes, add bias, optional sigmoid, coalesced store
    float bias[8];
#pragma unroll
    for (int j = 0; j < 8; j++) {
        int n = n0 + tx * 8 + j;
        bias[j] = b1[n] + (b2 ? b2[n] : 0.0f);
    }
#pragma unroll
    for (int i = 0; i < 8; i++) {
        float o[8];
#pragma unroll
        for (int j = 0; j < 8; j++) {
            float2 s = upk(acc[i][j]);
            float v = (s.x + s.y) + bias[j];
            if (SIG) v = sigm(v);
            o[j] = v;
        }
        float* cp = C + (size_t)(m0 + ty * 8 + i) * N + n0 + tx * 8;
        *(float4*)cp       = make_float4(o[0], o[1], o[2], o[3]);
        *(float4*)(cp + 4) = make_float4(o[4], o[5], o[6], o[7]);
    }
}

// K1: xg = x @ W_ih^T + (b_ih + b_hh)
__global__ void __launch_bounds__(256, 1)
k_xg(const float* __restrict__ x, const float* __restrict__ Wih,
     const float* __restrict__ bih, const float* __restrict__ bhh) {
    gemm_body<INPUT_, GATES_, false>(x, Wih, bih, bhh, g_xg);
}

// K3: out = sigmoid(hs @ W_out^T + b_out)
__global__ void __launch_bounds__(256, 1)
k_out(const float* __restrict__ Wout, const float* __restrict__ bout,
      float* __restrict__ out) {
    gemm_body<HID_, OUT_, true>(g_hs, Wout, bout, nullptr, out);
}

// K2: LSTM recurrence. One CTA per batch element; thread tid owns gate row tid.
__global__ void __launch_bounds__(256, 1)
k_lstm(const float* __restrict__ h0, const float* __restrict__ c0,
       const float* __restrict__ Whh,
       float* __restrict__ hT, float* __restrict__ cT) {
    const int b = blockIdx.x;
    const int tid = threadIdx.x;

    // W_hh row for this gate, packed as 32 f32x2 pairs (64 registers)
    unsigned long long w2[32];
    const float4* wr = (const float4*)(Whh + tid * HID_);
#pragma unroll
    for (int q = 0; q < 16; q++) {
        float4 v = wr[q];
        w2[2 * q]     = pk(v.x, v.y);
        w2[2 * q + 1] = pk(v.z, v.w);
    }

    __shared__ __align__(16) float hsh[HID_];
    __shared__ float act[GATES_];

    float c = 0.0f;
    if (tid < HID_) {
        hsh[tid] = h0[b * HID_ + tid];
        c = c0[b * HID_ + tid];
    }
    __syncthreads();

    const float* xp = g_xg + (size_t)b * GATES_ + tid;  // step stride BATCH*GATES_
    float xv = xp[0];

    for (int t = 0; t < T_STEPS; t++) {
        // Prefetch next step's gate pre-activation (hides DRAM latency)
        float xnext = 0.0f;
        if (t < T_STEPS - 1) xnext = xp[(size_t)(t + 1) * (BATCH * GATES_)];

        // gate = xv + dot(W_hh[tid,:], h)   via f32x2 packed FMAs
        unsigned long long a0 = 0ull, a1 = 0ull;
        const ulonglong2* hp = (const ulonglong2*)hsh;
#pragma unroll
        for (int q = 0; q < 16; q++) {
            ulonglong2 hh = hp[q];
            fma2(a0, w2[2 * q], hh.x);
            fma2(a1, w2[2 * q + 1], hh.y);
        }
        float2 s0 = upk(a0), s1 = upk(a1);
        float s = xv + ((s0.x + s0.y) + (s1.x + s1.y));

        // Gate order i,f,g,o: g (128..191) -> tanh, others -> sigmoid
        float a = (tid >= 128 && tid < 192) ? tanhf(s) : sigm(s);
        act[tid] = a;
        __syncthreads();

        if (tid < HID_) {
            float i_ = act[tid];
            float f_ = act[HID_ + tid];
            float g_ = act[2 * HID_ + tid];
            float o_ = act[3 * HID_ + tid];
            c = f_ * c + i_ * g_;
            float h = o_ * tanhf(c);
            hsh[tid] = h;
            g_hs[((size_t)t * BATCH + b) * HID_ + tid] = h;
        }
        __syncthreads();
        xv = xnext;
    }

    if (tid < HID_) {
        hT[b * HID_ + tid] = hsh[tid];
        cT[b * HID_ + tid] = c;
    }
}

extern "C" void kernel_launch(void* const* d_in, const int* in_sizes, int n_in,
                              void* d_out, int out_size) {
    const float* x    = (const float*)d_in[0];
    const float* h0   = (const float*)d_in[1];
    const float* c0   = (const float*)d_in[2];
    const float* Wih  = (const float*)d_in[3];
    const float* Whh  = (const float*)d_in[4];
    const float* bih  = (const float*)d_in[5];
    const float* bhh  = (const float*)d_in[6];
    const float* Wout = (const float*)d_in[7];
    const float* bout = (const float*)d_in[8];

    float* out = (float*)d_out;                 // (T, B, OUT)
    float* hT  = out + OUT_ELEMS;               // (1, B, HID)
    float* cT  = hT + HC_ELEMS;                 // (1, B, HID)

    // 1) xg = x @ W_ih^T + (b_ih + b_hh)
    k_xg<<<dim3(GATES_ / 128, M_ROWS / 128), 256>>>(x, Wih, bih, bhh);
    // 2) sequential LSTM recurrence (one CTA per batch element)
    k_lstm<<<BATCH, 256>>>(h0, c0, Whh, hT, cT);
    // 3) out = sigmoid(hs @ W_out^T + b_out)
    k_out<<<dim3(OUT_ / 128, M_ROWS / 128), 256>>>(Wout, bout, out);
}

// round 11
// speedup vs baseline: 1.3556x; 1.3556x over previous
#include <cuda_runtime.h>
#include <cuda_bf16.h>
#include <cstdint>

// ---------------- Problem constants ----------------
#define T_STEPS 512
#define BATCH   256
#define INPUT_  256
#define HID_    64
#define GATES_  256            // 4*HID
#define OUT_    1024
#define M_ROWS  (T_STEPS * BATCH)          // 131072
#define OUT_ELEMS ((size_t)M_ROWS * OUT_)
#define HC_ELEMS  (BATCH * HID_)

// Scratch (allocation-free rule: __device__ globals)
__device__ float g_xg[(size_t)M_ROWS * GATES_];  // x @ W_ih^T + (b_ih+b_hh)
__device__ float g_hs[(size_t)M_ROWS * HID_];    // per-step hidden states

// ---------------- helpers ----------------
__device__ __forceinline__ uint32_t smem_u32(const void* p) {
    uint32_t a;
    asm("{ .reg .u64 t; cvta.to.shared.u64 t, %1; cvt.u32.u64 %0, t; }"
        : "=r"(a) : "l"(p));
    return a;
}
__device__ __forceinline__ float sigm(float x) { return 1.0f / (1.0f + __expf(-x)); }

// Warp-level tensor ops — plain-target PTX (sm_80+), no 'a' features.
#define LDMX4(r, addr) \
    asm volatile("ldmatrix.sync.aligned.m8n8.x4.shared.b16 {%0,%1,%2,%3}, [%4];" \
        : "=r"((r)[0]), "=r"((r)[1]), "=r"((r)[2]), "=r"((r)[3]) : "r"(addr))

#define MMA16816(d, a, b) \
    asm volatile("mma.sync.aligned.m16n8k16.row.col.f32.bf16.bf16.f32 " \
        "{%0,%1,%2,%3}, {%4,%5,%6,%7}, {%8,%9}, {%0,%1,%2,%3};" \
        : "+f"((d)[0]), "+f"((d)[1]), "+f"((d)[2]), "+f"((d)[3]) \
        : "r"((a)[0]), "r"((a)[1]), "r"((a)[2]), "r"((a)[3]), \
          "r"((b)[0]), "r"((b)[1]))

// ---------------- f32x2 packed-FMA helpers (LSTM recurrence) ----------------
__device__ __forceinline__ unsigned long long pk(float x, float y) {
    unsigned long long r;
    asm("mov.b64 %0, {%1, %2};" : "=l"(r) : "f"(x), "f"(y));
    return r;
}
__device__ __forceinline__ void fma2(unsigned long long& d,
                                     unsigned long long a, unsigned long long b) {
    asm("fma.rn.f32x2 %0, %1, %2, %0;" : "+l"(d) : "l"(a), "l"(b));
}
__device__ __forceinline__ float2 upk(unsigned long long v) {
    float2 r;
    asm("mov.b64 {%0, %1}, %2;" : "=f"(r.x), "=f"(r.y) : "l"(v));
    return r;
}

// ---------------- bf16 2-way split convert + smem store ----------------
// Row stride 80B: consecutive rows start 20 banks apart -> any 8 consecutive
// rows hit disjoint bank groups => conflict-free ldmatrix phases.
#define SM_LDR 80
__device__ __forceinline__ void cvt_store(char* hi, char* lo, int row, int c4, float4 v) {
    __nv_bfloat162 h01 = __float22bfloat162_rn(make_float2(v.x, v.y));
    __nv_bfloat162 h23 = __float22bfloat162_rn(make_float2(v.z, v.w));
    float2 r01 = make_float2(v.x - __bfloat162float(h01.x), v.y - __bfloat162float(h01.y));
    float2 r23 = make_float2(v.z - __bfloat162float(h23.x), v.w - __bfloat162float(h23.y));
    __nv_bfloat162 l01 = __float22bfloat162_rn(r01);
    __nv_bfloat162 l23 = __float22bfloat162_rn(r23);
    uint32_t off = (uint32_t)(row * SM_LDR + c4 * 8);
    uint2 hv, lv;
    hv.x = *(uint32_t*)&h01; hv.y = *(uint32_t*)&h23;
    lv.x = *(uint32_t*)&l01; lv.y = *(uint32_t*)&l23;
    *(uint2*)(hi + off) = hv;
    *(uint2*)(lo + off) = lv;
}

// ---------------- mma.sync GEMM body ----------------
// C[m][n] = act( A[m][K] . B[n][K]^T + bias ), CTA tile 128x128, BK=32.
// Split-2 bf16: D = Ahi*Bhi + Ahi*Blo + Alo*Bhi (fp32 accumulate in regs).
// 8 warps as 4(M) x 2(N); warp tile 32x64 = 2x8 m16n8k16 tiles.
template <int K, int CLD, bool SIG>
__device__ __forceinline__ void gemm_mma_body(const float* __restrict__ A,
                                              const float* __restrict__ Bm,
                                              const float* __restrict__ b1,
                                              const float* __restrict__ b2,
                                              float* __restrict__ C,
                                              int m0, int n0) {
    __shared__ __align__(16) char sm[4 * 128 * SM_LDR];   // 40 KB
    char* A_hi = sm;
    char* A_lo = sm + 128 * SM_LDR;
    char* B_hi = sm + 2 * 128 * SM_LDR;
    char* B_lo = sm + 3 * 128 * SM_LDR;

    const int tid  = threadIdx.x;
    const int lane = tid & 31;
    const int warp = tid >> 5;
    const int wm = (warp & 3) * 32;   // warp M offset within tile
    const int wn = (warp >> 2) * 64;  // warp N offset within tile

    float acc[2][8][4];
#pragma unroll
    for (int i = 0; i < 2; i++)
#pragma unroll
        for (int j = 0; j < 8; j++)
#pragma unroll
            for (int q = 0; q < 4; q++) acc[i][j][q] = 0.0f;

    // Per-thread global load coords: 4 rows (i*32 + tid>>3), float4 col tid&7
    const int lrow = tid >> 3;
    const int lc4  = tid & 7;

    // ldmatrix lane-dependent address components
    const uint32_t aHiB = smem_u32(A_hi), aLoB = smem_u32(A_lo);
    const uint32_t bHiB = smem_u32(B_hi), bLoB = smem_u32(B_lo);
    // A x4: lanes 0-15 -> rows 0-15 (k-lo 16B), lanes 16-31 -> rows 0-15 (k-hi)
    const uint32_t aoff = (uint32_t)((wm + (lane & 15)) * SM_LDR + (lane >> 4) * 16);
    // B x4: m0 lanes0-7 (n0-7,k-lo), m1 8-15 (n0-7,k-hi), m2 (n8-15,k-lo), m3 (n8-15,k-hi)
    const uint32_t boff = (uint32_t)((wn + (lane & 7) + ((lane >> 4) & 1) * 8) * SM_LDR
                                     + ((lane >> 3) & 1) * 16);

    // Prefetch iteration 0
    float4 pa[4], pb[4];
#pragma unroll
    for (int i = 0; i < 4; i++) {
        pa[i] = *(const float4*)(A  + (size_t)(m0 + lrow + i * 32) * K + lc4 * 4);
        pb[i] = *(const float4*)(Bm + (size_t)(n0 + lrow + i * 32) * K + lc4 * 4);
    }

    for (int kt = 0; kt < K; kt += 32) {
        __syncthreads();   // previous compute done before overwriting smem
#pragma unroll
        for (int i = 0; i < 4; i++) {
            cvt_store(A_hi, A_lo, lrow + i * 32, lc4, pa[i]);
            cvt_store(B_hi, B_lo, lrow + i * 32, lc4, pb[i]);
        }
        __syncthreads();
        if (kt + 32 < K) {   // prefetch next tile, overlaps compute below
#pragma unroll
            for (int i = 0; i < 4; i++) {
                pa[i] = *(const float4*)(A  + (size_t)(m0 + lrow + i * 32) * K + kt + 32 + lc4 * 4);
                pb[i] = *(const float4*)(Bm + (size_t)(n0 + lrow + i * 32) * K + kt + 32 + lc4 * 4);
            }
        }

#pragma unroll
        for (int k16 = 0; k16 < 2; k16++) {
            uint32_t ah[2][4], al[2][4], bh[8][2], bl[8][2];
#pragma unroll
            for (int mi = 0; mi < 2; mi++) {
                uint32_t d = aoff + mi * (16 * SM_LDR) + k16 * 32;
                LDMX4(ah[mi], aHiB + d);
                LDMX4(al[mi], aLoB + d);
            }
#pragma unroll
            for (int njp = 0; njp < 4; njp++) {   // each x4 covers two n8 tiles
                uint32_t d = boff + njp * (16 * SM_LDR) + k16 * 32;
                uint32_t th[4], tl[4];
                LDMX4(th, bHiB + d);
                LDMX4(tl, bLoB + d);
                bh[2 * njp][0] = th[0]; bh[2 * njp][1] = th[1];
                bh[2 * njp + 1][0] = th[2]; bh[2 * njp + 1][1] = th[3];
                bl[2 * njp][0] = tl[0]; bl[2 * njp][1] = tl[1];
                bl[2 * njp + 1][0] = tl[2]; bl[2 * njp + 1][1] = tl[3];
            }
#pragma unroll
            for (int mi = 0; mi < 2; mi++)
#pragma unroll
                for (int nj = 0; nj < 8; nj++) {
                    MMA16816(acc[mi][nj], ah[mi], bh[nj]);
                    MMA16816(acc[mi][nj], ah[mi], bl[nj]);
                    MMA16816(acc[mi][nj], al[mi], bh[nj]);
                }
        }
    }

    // Epilogue: acc frag (c0,c1)=row r cols 2c,2c+1; (c2,c3)=row r+8
    const int er = lane >> 2;
    const int ec = (lane & 3) * 2;
#pragma unroll
    for (int nj = 0; nj < 8; nj++) {
        int n = n0 + wn + nj * 8 + ec;
        float bb0 = b1[n]     + (b2 ? b2[n]     : 0.0f);
        float bb1 = b1[n + 1] + (b2 ? b2[n + 1] : 0.0f);
#pragma unroll
        for (int mi = 0; mi < 2; mi++) {
            int r0 = m0 + wm + mi * 16 + er;
            float v0 = acc[mi][nj][0] + bb0;
            float v1 = acc[mi][nj][1] + bb1;
            float v2 = acc[mi][nj][2] + bb0;
            float v3 = acc[mi][nj][3] + bb1;
            if (SIG) { v0 = sigm(v0); v1 = sigm(v1); v2 = sigm(v2); v3 = sigm(v3); }
            *(float2*)(C + (size_t)r0 * CLD + n)       = make_float2(v0, v1);
            *(float2*)(C + (size_t)(r0 + 8) * CLD + n) = make_float2(v2, v3);
        }
    }
}

// K1: xg = x @ W_ih^T + (b_ih + b_hh)   (M=131072, N=256, K=256)
__global__ void __launch_bounds__(256)
k_xg_mma(const float* __restrict__ x, const float* __restrict__ Wih,
         const float* __restrict__ bih, const float* __restrict__ bhh) {
    gemm_mma_body<INPUT_, GATES_, false>(x, Wih, bih, bhh, g_xg,
                                         blockIdx.y * 128, blockIdx.x * 128);
}

// K3: out = sigmoid(hs @ W_out^T + b_out)   (M=131072, N=1024, K=64)
__global__ void __launch_bounds__(256)
k_out_mma(const float* __restrict__ Wout, const float* __restrict__ bout,
          float* __restrict__ out) {
    gemm_mma_body<HID_, OUT_, true>(g_hs, Wout, bout, nullptr, out,
                                    blockIdx.y * 128, blockIdx.x * 128);
}

// ---------------- K2: LSTM recurrence ----------------
// One CTA per batch element; thread tid owns gate row tid of W_hh.
// 4-deep xg prefetch (MLP=4 covers DRAM latency), 4 independent FMA2 chains.
__global__ void __launch_bounds__(256, 1)
k_lstm(const float* __restrict__ h0, const float* __restrict__ c0,
       const float* __restrict__ Whh,
       float* __restrict__ hT, float* __restrict__ cT) {
    const int b = blockIdx.x;
    const int tid = threadIdx.x;

    unsigned long long w2[32];
    const float4* wr = (const float4*)(Whh + tid * HID_);
#pragma unroll
    for (int q = 0; q < 16; q++) {
        float4 v = wr[q];
        w2[2 * q]     = pk(v.x, v.y);
        w2[2 * q + 1] = pk(v.z, v.w);
    }

    __shared__ __align__(16) float hsh[HID_];
    __shared__ float act[GATES_];

    float c = 0.0f;
    if (tid < HID_) {
        hsh[tid] = h0[b * HID_ + tid];
        c = c0[b * HID_ + tid];
    }
    __syncthreads();

    const float* xp = g_xg + (size_t)b * GATES_ + tid;  // step stride BATCH*GATES_

#define XLD(tq) (((tq) < T_STEPS) ? xp[(size_t)(tq) * (BATCH * GATES_)] : 0.0f)

#define LSTM_STEP(XV, T)                                                        \
    do {                                                                        \
        unsigned long long a0 = 0, a1 = 0, a2 = 0, a3 = 0;                      \
        const ulonglong2* hp = (const ulonglong2*)hsh;                          \
        _Pragma("unroll")                                                       \
        for (int q = 0; q < 8; q++) {                                           \
            ulonglong2 hA = hp[2 * q], hB = hp[2 * q + 1];                      \
            fma2(a0, w2[4 * q],     hA.x);                                      \
            fma2(a1, w2[4 * q + 1], hA.y);                                      \
            fma2(a2, w2[4 * q + 2], hB.x);                                      \
            fma2(a3, w2[4 * q + 3], hB.y);                                      \
        }                                                                       \
        float2 s0 = upk(a0), s1 = upk(a1), s2 = upk(a2), s3 = upk(a3);          \
        float s = (XV) + (((s0.x + s0.y) + (s1.x + s1.y)) +                     \
                          ((s2.x + s2.y) + (s3.x + s3.y)));                     \
        float a = (tid >= 128 && tid < 192) ? tanhf(s) : sigm(s);               \
        act[tid] = a;                                                           \
        __syncthreads();                                                        \
        if (tid < HID_) {                                                       \
            float i_ = act[tid];                                                \
            float f_ = act[HID_ + tid];                                         \
            float g_ = act[2 * HID_ + tid];                                     \
            float o_ = act[3 * HID_ + tid];                                     \
            c = f_ * c + i_ * g_;                                               \
            float h = o_ * tanhf(c);                                            \
            hsh[tid] = h;                                                       \
            g_hs[((size_t)(T) * BATCH + b) * HID_ + tid] = h;                   \
        }                                                                       \
        __syncthreads();                                                        \
    } while (0)

    float x0 = XLD(0), x1 = XLD(1), x2 = XLD(2), x3 = XLD(3);
    for (int t = 0; t < T_STEPS; t += 4) {
        float n0_ = XLD(t + 4), n1_ = XLD(t + 5), n2_ = XLD(t + 6), n3_ = XLD(t + 7);
        LSTM_STEP(x0, t);
        LSTM_STEP(x1, t + 1);
        LSTM_STEP(x2, t + 2);
        LSTM_STEP(x3, t + 3);
        x0 = n0_; x1 = n1_; x2 = n2_; x3 = n3_;
    }

    if (tid < HID_) {
        hT[b * HID_ + tid] = hsh[tid];
        cT[b * HID_ + tid] = c;
    }
#undef LSTM_STEP
#undef XLD
}

extern "C" void kernel_launch(void* const* d_in, const int* in_sizes, int n_in,
                              void* d_out, int out_size) {
    const float* x    = (const float*)d_in[0];
    const float* h0   = (const float*)d_in[1];
    const float* c0   = (const float*)d_in[2];
    const float* Wih  = (const float*)d_in[3];
    const float* Whh  = (const float*)d_in[4];
    const float* bih  = (const float*)d_in[5];
    const float* bhh  = (const float*)d_in[6];
    const float* Wout = (const float*)d_in[7];
    const float* bout = (const float*)d_in[8];

    float* out = (float*)d_out;
    float* hT  = out + OUT_ELEMS;
    float* cT  = hT + HC_ELEMS;

    // 1) xg = x @ W_ih^T + (b_ih + b_hh)   — bf16 split-2 on tensor cores
    k_xg_mma<<<dim3(GATES_ / 128, M_ROWS / 128), 256>>>(x, Wih, bih, bhh);
    // 2) sequential LSTM recurrence
    k_lstm<<<BATCH, 256>>>(h0, c0, Whh, hT, cT);
    // 3) out = sigmoid(hs @ W_out^T + b_out) — bf16 split-2 on tensor cores
    k_out_mma<<<dim3(OUT_ / 128, M_ROWS / 128), 256>>>(Wout, bout, out);
}

// round 12
// speedup vs baseline: 1.3569x; 1.0009x over previous
#include <cuda_runtime.h>
#include <cuda_bf16.h>
#include <cstdint>

// ---------------- Problem constants ----------------
#define T_STEPS 512
#define BATCH   256
#define INPUT_  256
#define HID_    64
#define GATES_  256            // 4*HID
#define OUT_    1024
#define M_ROWS  (T_STEPS * BATCH)          // 131072
#define OUT_ELEMS ((size_t)M_ROWS * OUT_)
#define HC_ELEMS  (BATCH * HID_)

// Scratch (allocation-free rule: __device__ globals)
__device__ float g_xg[(size_t)M_ROWS * GATES_];  // x @ W_ih^T + (b_ih+b_hh)
__device__ float g_hs[(size_t)M_ROWS * HID_];    // per-step hidden states

// ---------------- helpers ----------------
__device__ __forceinline__ uint32_t smem_u32(const void* p) {
    uint32_t a;
    asm("{ .reg .u64 t; cvta.to.shared.u64 t, %1; cvt.u32.u64 %0, t; }"
        : "=r"(a) : "l"(p));
    return a;
}
__device__ __forceinline__ float sigm(float x) { return 1.0f / (1.0f + __expf(-x)); }

// Warp-level tensor ops — plain-target PTX (sm_80+), no 'a' features.
#define LDMX4(r, addr) \
    asm volatile("ldmatrix.sync.aligned.m8n8.x4.shared.b16 {%0,%1,%2,%3}, [%4];" \
        : "=r"((r)[0]), "=r"((r)[1]), "=r"((r)[2]), "=r"((r)[3]) : "r"(addr))

#define MMA16816(d, a, b) \
    asm volatile("mma.sync.aligned.m16n8k16.row.col.f32.bf16.bf16.f32 " \
        "{%0,%1,%2,%3}, {%4,%5,%6,%7}, {%8,%9}, {%0,%1,%2,%3};" \
        : "+f"((d)[0]), "+f"((d)[1]), "+f"((d)[2]), "+f"((d)[3]) \
        : "r"((a)[0]), "r"((a)[1]), "r"((a)[2]), "r"((a)[3]), \
          "r"((b)[0]), "r"((b)[1]))

// ---------------- f32x2 packed-FMA helpers (LSTM recurrence) ----------------
__device__ __forceinline__ unsigned long long pk(float x, float y) {
    unsigned long long r;
    asm("mov.b64 %0, {%1, %2};" : "=l"(r) : "f"(x), "f"(y));
    return r;
}
__device__ __forceinline__ void fma2(unsigned long long& d,
                                     unsigned long long a, unsigned long long b) {
    asm("fma.rn.f32x2 %0, %1, %2, %0;" : "+l"(d) : "l"(a), "l"(b));
}
__device__ __forceinline__ float2 upk(unsigned long long v) {
    float2 r;
    asm("mov.b64 {%0, %1}, %2;" : "=f"(r.x), "=f"(r.y) : "l"(v));
    return r;
}

// ---------------- bf16 2-way split convert + smem store ----------------
// Row stride 80B: consecutive rows start 20 banks apart -> any 8 consecutive
// rows hit disjoint bank groups => conflict-free ldmatrix phases.
#define SM_LDR 80
__device__ __forceinline__ void cvt_store(char* hi, char* lo, int row, int c4, float4 v) {
    __nv_bfloat162 h01 = __float22bfloat162_rn(make_float2(v.x, v.y));
    __nv_bfloat162 h23 = __float22bfloat162_rn(make_float2(v.z, v.w));
    float2 r01 = make_float2(v.x - __bfloat162float(h01.x), v.y - __bfloat162float(h01.y));
    float2 r23 = make_float2(v.z - __bfloat162float(h23.x), v.w - __bfloat162float(h23.y));
    __nv_bfloat162 l01 = __float22bfloat162_rn(r01);
    __nv_bfloat162 l23 = __float22bfloat162_rn(r23);
    uint32_t off = (uint32_t)(row * SM_LDR + c4 * 8);
    uint2 hv, lv;
    hv.x = *(uint32_t*)&h01; hv.y = *(uint32_t*)&h23;
    lv.x = *(uint32_t*)&l01; lv.y = *(uint32_t*)&l23;
    *(uint2*)(hi + off) = hv;
    *(uint2*)(lo + off) = lv;
}

// ---------------- mma.sync GEMM body ----------------
// C[m][n] = act( A[m][K] . B[n][K]^T + bias ), CTA tile 128x128, BK=32.
// Split-2 bf16: D = Ahi*Bhi + Ahi*Blo + Alo*Bhi (fp32 accumulate in regs).
// 8 warps as 4(M) x 2(N); warp tile 32x64 = 2x8 m16n8k16 tiles.
template <int K, int CLD, bool SIG>
__device__ __forceinline__ void gemm_mma_body(const float* __restrict__ A,
                                              const float* __restrict__ Bm,
                                              const float* __restrict__ b1,
                                              const float* __restrict__ b2,
                                              float* __restrict__ C,
                                              int m0, int n0) {
    __shared__ __align__(16) char sm[4 * 128 * SM_LDR];   // 40 KB
    char* A_hi = sm;
    char* A_lo = sm + 128 * SM_LDR;
    char* B_hi = sm + 2 * 128 * SM_LDR;
    char* B_lo = sm + 3 * 128 * SM_LDR;

    const int tid  = threadIdx.x;
    const int lane = tid & 31;
    const int warp = tid >> 5;
    const int wm = (warp & 3) * 32;   // warp M offset within tile
    const int wn = (warp >> 2) * 64;  // warp N offset within tile

    float acc[2][8][4];
#pragma unroll
    for (int i = 0; i < 2; i++)
#pragma unroll
        for (int j = 0; j < 8; j++)
#pragma unroll
            for (int q = 0; q < 4; q++) acc[i][j][q] = 0.0f;

    // Per-thread global load coords: 4 rows (i*32 + tid>>3), float4 col tid&7
    const int lrow = tid >> 3;
    const int lc4  = tid & 7;

    // ldmatrix lane-dependent address components
    const uint32_t aHiB = smem_u32(A_hi), aLoB = smem_u32(A_lo);
    const uint32_t bHiB = smem_u32(B_hi), bLoB = smem_u32(B_lo);
    // A x4: lanes 0-15 -> rows 0-15 (k-lo 16B), lanes 16-31 -> rows 0-15 (k-hi)
    const uint32_t aoff = (uint32_t)((wm + (lane & 15)) * SM_LDR + (lane >> 4) * 16);
    // B x4: m0 lanes0-7 (n0-7,k-lo), m1 8-15 (n0-7,k-hi), m2 (n8-15,k-lo), m3 (n8-15,k-hi)
    const uint32_t boff = (uint32_t)((wn + (lane & 7) + ((lane >> 4) & 1) * 8) * SM_LDR
                                     + ((lane >> 3) & 1) * 16);

    // Prefetch iteration 0
    float4 pa[4], pb[4];
#pragma unroll
    for (int i = 0; i < 4; i++) {
        pa[i] = *(const float4*)(A  + (size_t)(m0 + lrow + i * 32) * K + lc4 * 4);
        pb[i] = *(const float4*)(Bm + (size_t)(n0 + lrow + i * 32) * K + lc4 * 4);
    }

    for (int kt = 0; kt < K; kt += 32) {
        __syncthreads();   // previous compute done before overwriting smem
#pragma unroll
        for (int i = 0; i < 4; i++) {
            cvt_store(A_hi, A_lo, lrow + i * 32, lc4, pa[i]);
            cvt_store(B_hi, B_lo, lrow + i * 32, lc4, pb[i]);
        }
        __syncthreads();
        if (kt + 32 < K) {   // prefetch next tile, overlaps compute below
#pragma unroll
            for (int i = 0; i < 4; i++) {
                pa[i] = *(const float4*)(A  + (size_t)(m0 + lrow + i * 32) * K + kt + 32 + lc4 * 4);
                pb[i] = *(const float4*)(Bm + (size_t)(n0 + lrow + i * 32) * K + kt + 32 + lc4 * 4);
            }
        }

#pragma unroll
        for (int k16 = 0; k16 < 2; k16++) {
            uint32_t ah[2][4], al[2][4], bh[8][2], bl[8][2];
#pragma unroll
            for (int mi = 0; mi < 2; mi++) {
                uint32_t d = aoff + mi * (16 * SM_LDR) + k16 * 32;
                LDMX4(ah[mi], aHiB + d);
                LDMX4(al[mi], aLoB + d);
            }
#pragma unroll
            for (int njp = 0; njp < 4; njp++) {   // each x4 covers two n8 tiles
                uint32_t d = boff + njp * (16 * SM_LDR) + k16 * 32;
                uint32_t th[4], tl[4];
                LDMX4(th, bHiB + d);
                LDMX4(tl, bLoB + d);
                bh[2 * njp][0] = th[0]; bh[2 * njp][1] = th[1];
                bh[2 * njp + 1][0] = th[2]; bh[2 * njp + 1][1] = th[3];
                bl[2 * njp][0] = tl[0]; bl[2 * njp][1] = tl[1];
                bl[2 * njp + 1][0] = tl[2]; bl[2 * njp + 1][1] = tl[3];
            }
#pragma unroll
            for (int mi = 0; mi < 2; mi++)
#pragma unroll
                for (int nj = 0; nj < 8; nj++) {
                    MMA16816(acc[mi][nj], ah[mi], bh[nj]);
                    MMA16816(acc[mi][nj], ah[mi], bl[nj]);
                    MMA16816(acc[mi][nj], al[mi], bh[nj]);
                }
        }
    }

    // Epilogue: acc frag (c0,c1)=row r cols 2c,2c+1; (c2,c3)=row r+8
    const int er = lane >> 2;
    const int ec = (lane & 3) * 2;
#pragma unroll
    for (int nj = 0; nj < 8; nj++) {
        int n = n0 + wn + nj * 8 + ec;
        float bb0 = b1[n]     + (b2 ? b2[n]     : 0.0f);
        float bb1 = b1[n + 1] + (b2 ? b2[n + 1] : 0.0f);
#pragma unroll
        for (int mi = 0; mi < 2; mi++) {
            int r0 = m0 + wm + mi * 16 + er;
            float v0 = acc[mi][nj][0] + bb0;
            float v1 = acc[mi][nj][1] + bb1;
            float v2 = acc[mi][nj][2] + bb0;
            float v3 = acc[mi][nj][3] + bb1;
            if (SIG) { v0 = sigm(v0); v1 = sigm(v1); v2 = sigm(v2); v3 = sigm(v3); }
            *(float2*)(C + (size_t)r0 * CLD + n)       = make_float2(v0, v1);
            *(float2*)(C + (size_t)(r0 + 8) * CLD + n) = make_float2(v2, v3);
        }
    }
}

// K1: xg = x @ W_ih^T + (b_ih + b_hh)   (M=131072, N=256, K=256)
__global__ void __launch_bounds__(256)
k_xg_mma(const float* __restrict__ x, const float* __restrict__ Wih,
         const float* __restrict__ bih, const float* __restrict__ bhh) {
    gemm_mma_body<INPUT_, GATES_, false>(x, Wih, bih, bhh, g_xg,
                                         blockIdx.y * 128, blockIdx.x * 128);
}

// K3: out = sigmoid(hs @ W_out^T + b_out)   (M=131072, N=1024, K=64)
__global__ void __launch_bounds__(256)
k_out_mma(const float* __restrict__ Wout, const float* __restrict__ bout,
          float* __restrict__ out) {
    gemm_mma_body<HID_, OUT_, true>(g_hs, Wout, bout, nullptr, out,
                                    blockIdx.y * 128, blockIdx.x * 128);
}

// ---------------- K2: LSTM recurrence ----------------
// One CTA per batch element; thread tid owns gate row tid of W_hh.
// 4-deep xg prefetch (MLP=4 covers DRAM latency), 4 independent FMA2 chains.
__global__ void __launch_bounds__(256, 1)
k_lstm(const float* __restrict__ h0, const float* __restrict__ c0,
       const float* __restrict__ Whh,
       float* __restrict__ hT, float* __restrict__ cT) {
    const int b = blockIdx.x;
    const int tid = threadIdx.x;

    unsigned long long w2[32];
    const float4* wr = (const float4*)(Whh + tid * HID_);
#pragma unroll
    for (int q = 0; q < 16; q++) {
        float4 v = wr[q];
        w2[2 * q]     = pk(v.x, v.y);
        w2[2 * q + 1] = pk(v.z, v.w);
    }

    __shared__ __align__(16) float hsh[HID_];
    __shared__ float act[GATES_];

    float c = 0.0f;
    if (tid < HID_) {
        hsh[tid] = h0[b * HID_ + tid];
        c = c0[b * HID_ + tid];
    }
    __syncthreads();

    const float* xp = g_xg + (size_t)b * GATES_ + tid;  // step stride BATCH*GATES_

#define XLD(tq) (((tq) < T_STEPS) ? xp[(size_t)(tq) * (BATCH * GATES_)] : 0.0f)

#define LSTM_STEP(XV, T)                                                        \
    do {                                                                        \
        unsigned long long a0 = 0, a1 = 0, a2 = 0, a3 = 0;                      \
        const ulonglong2* hp = (const ulonglong2*)hsh;                          \
        _Pragma("unroll")                                                       \
        for (int q = 0; q < 8; q++) {                                           \
            ulonglong2 hA = hp[2 * q], hB = hp[2 * q + 1];                      \
            fma2(a0, w2[4 * q],     hA.x);                                      \
            fma2(a1, w2[4 * q + 1], hA.y);                                      \
            fma2(a2, w2[4 * q + 2], hB.x);                                      \
            fma2(a3, w2[4 * q + 3], hB.y);                                      \
        }                                                                       \
        float2 s0 = upk(a0), s1 = upk(a1), s2 = upk(a2), s3 = upk(a3);          \
        float s = (XV) + (((s0.x + s0.y) + (s1.x + s1.y)) +                     \
                          ((s2.x + s2.y) + (s3.x + s3.y)));                     \
        float a = (tid >= 128 && tid < 192) ? tanhf(s) : sigm(s);               \
        act[tid] = a;                                                           \
        __syncthreads();                                                        \
        if (tid < HID_) {                                                       \
            float i_ = act[tid];                                                \
            float f_ = act[HID_ + tid];                                         \
            float g_ = act[2 * HID_ + tid];                                     \
            float o_ = act[3 * HID_ + tid];                                     \
            c = f_ * c + i_ * g_;                                               \
            float h = o_ * tanhf(c);                                            \
            hsh[tid] = h;                                                       \
            g_hs[((size_t)(T) * BATCH + b) * HID_ + tid] = h;                   \
        }                                                                       \
        __syncthreads();                                                        \
    } while (0)

    float x0 = XLD(0), x1 = XLD(1), x2 = XLD(2), x3 = XLD(3);
    for (int t = 0; t < T_STEPS; t += 4) {
        float n0_ = XLD(t + 4), n1_ = XLD(t + 5), n2_ = XLD(t + 6), n3_ = XLD(t + 7);
        LSTM_STEP(x0, t);
        LSTM_STEP(x1, t + 1);
        LSTM_STEP(x2, t + 2);
        LSTM_STEP(x3, t + 3);
        x0 = n0_; x1 = n1_; x2 = n2_; x3 = n3_;
    }

    if (tid < HID_) {
        hT[b * HID_ + tid] = hsh[tid];
        cT[b * HID_ + tid] = c;
    }
#undef LSTM_STEP
#undef XLD
}

extern "C" void kernel_launch(void* const* d_in, const int* in_sizes, int n_in,
                              void* d_out, int out_size) {
    const float* x    = (const float*)d_in[0];
    const float* h0   = (const float*)d_in[1];
    const float* c0   = (const float*)d_in[2];
    const float* Wih  = (const float*)d_in[3];
    const float* Whh  = (const float*)d_in[4];
    const float* bih  = (const float*)d_in[5];
    const float* bhh  = (const float*)d_in[6];
    const float* Wout = (const float*)d_in[7];
    const float* bout = (const float*)d_in[8];

    float* out = (float*)d_out;
    float* hT  = out + OUT_ELEMS;
    float* cT  = hT + HC_ELEMS;

    // 1) xg = x @ W_ih^T + (b_ih + b_hh)   — bf16 split-2 on tensor cores
    k_xg_mma<<<dim3(GATES_ / 128, M_ROWS / 128), 256>>>(x, Wih, bih, bhh);
    // 2) sequential LSTM recurrence
    k_lstm<<<BATCH, 256>>>(h0, c0, Whh, hT, cT);
    // 3) out = sigmoid(hs @ W_out^T + b_out) — bf16 split-2 on tensor cores
    k_out_mma<<<dim3(OUT_ / 128, M_ROWS / 128), 256>>>(Wout, bout, out);
}

// round 13
// speedup vs baseline: 1.8579x; 1.3693x over previous
#include <cuda_runtime.h>
#include <cuda_bf16.h>
#include <cstdint>

// ---------------- Problem constants ----------------
#define T_STEPS 512
#define BATCH   256
#define INPUT_  256
#define HID_    64
#define GATES_  256            // 4*HID
#define OUT_    1024
#define M_ROWS  (T_STEPS * BATCH)          // 131072
#define OUT_ELEMS ((size_t)M_ROWS * OUT_)
#define HC_ELEMS  (BATCH * HID_)

// Scratch (allocation-free rule: __device__ globals)
__device__ float g_xg[(size_t)M_ROWS * GATES_];  // x @ W_ih^T + (b_ih+b_hh)
__device__ float g_hs[(size_t)M_ROWS * HID_];    // per-step hidden states

// ---------------- helpers ----------------
__device__ __forceinline__ uint32_t smem_u32(const void* p) {
    uint32_t a;
    asm("{ .reg .u64 t; cvta.to.shared.u64 t, %1; cvt.u32.u64 %0, t; }"
        : "=r"(a) : "l"(p));
    return a;
}
__device__ __forceinline__ float sigm(float x) { return 1.0f / (1.0f + __expf(-x)); }
__device__ __forceinline__ float tanh_fast(float x) {
    float y;
    asm("tanh.approx.f32 %0, %1;" : "=f"(y) : "f"(x));
    return y;
}

// Warp-level tensor ops — plain-target PTX (sm_80+), no 'a' features.
#define LDMX4(r, addr) \
    asm volatile("ldmatrix.sync.aligned.m8n8.x4.shared.b16 {%0,%1,%2,%3}, [%4];" \
        : "=r"((r)[0]), "=r"((r)[1]), "=r"((r)[2]), "=r"((r)[3]) : "r"(addr))

#define MMA16816(d, a, b) \
    asm volatile("mma.sync.aligned.m16n8k16.row.col.f32.bf16.bf16.f32 " \
        "{%0,%1,%2,%3}, {%4,%5,%6,%7}, {%8,%9}, {%0,%1,%2,%3};" \
        : "+f"((d)[0]), "+f"((d)[1]), "+f"((d)[2]), "+f"((d)[3]) \
        : "r"((a)[0]), "r"((a)[1]), "r"((a)[2]), "r"((a)[3]), \
          "r"((b)[0]), "r"((b)[1]))

// ---------------- f32x2 packed-FMA helpers (LSTM recurrence) ----------------
__device__ __forceinline__ unsigned long long pk(float x, float y) {
    unsigned long long r;
    asm("mov.b64 %0, {%1, %2};" : "=l"(r) : "f"(x), "f"(y));
    return r;
}
__device__ __forceinline__ void fma2(unsigned long long& d,
                                     unsigned long long a, unsigned long long b) {
    asm("fma.rn.f32x2 %0, %1, %2, %0;" : "+l"(d) : "l"(a), "l"(b));
}
__device__ __forceinline__ float2 upk(unsigned long long v) {
    float2 r;
    asm("mov.b64 {%0, %1}, %2;" : "=f"(r.x), "=f"(r.y) : "l"(v));
    return r;
}

// ---------------- bf16 2-way split convert + smem store ----------------
// Row stride 80B: consecutive rows start 20 banks apart -> any 8 consecutive
// rows of an ldmatrix phase hit disjoint banks.
#define SM_LDR 80
#define TILE_B (128 * SM_LDR)   // 10240 B per tile
__device__ __forceinline__ void cvt_store(char* hi, char* lo, int row, int c4, float4 v) {
    __nv_bfloat162 h01 = __float22bfloat162_rn(make_float2(v.x, v.y));
    __nv_bfloat162 h23 = __float22bfloat162_rn(make_float2(v.z, v.w));
    float2 r01 = make_float2(v.x - __bfloat162float(h01.x), v.y - __bfloat162float(h01.y));
    float2 r23 = make_float2(v.z - __bfloat162float(h23.x), v.w - __bfloat162float(h23.y));
    __nv_bfloat162 l01 = __float22bfloat162_rn(r01);
    __nv_bfloat162 l23 = __float22bfloat162_rn(r23);
    uint32_t off = (uint32_t)(row * SM_LDR + c4 * 8);
    uint2 hv, lv;
    hv.x = *(uint32_t*)&h01; hv.y = *(uint32_t*)&h23;
    lv.x = *(uint32_t*)&l01; lv.y = *(uint32_t*)&l23;
    *(uint2*)(hi + off) = hv;
    *(uint2*)(lo + off) = lv;
}

// ---------------- mma.sync GEMM body (512 threads, double-buffered) ----------
// C[m][n] = act( A[m][K] . B[n][K]^T + bias ), CTA tile 128x128, BK=32.
// Split-2 bf16: D = Ahi*Bhi + Ahi*Blo + Alo*Bhi (fp32 accumulate in regs).
// 16 warps as 4(M) x 4(N); warp tile 32x32 = 2x4 m16n8k16 tiles.
// Smem: 2 stages x 4 tiles (Ahi,Alo,Bhi,Blo) x 10240 B = 80 KB (dynamic).
template <int K, int CLD, bool SIG>
__device__ __forceinline__ void gemm_mma_body(const float* __restrict__ A,
                                              const float* __restrict__ Bm,
                                              const float* __restrict__ b1,
                                              const float* __restrict__ b2,
                                              float* __restrict__ C,
                                              int m0, int n0) {
    extern __shared__ char dsm[];
    const uint32_t smBase = smem_u32(dsm);

    const int tid  = threadIdx.x;
    const int lane = tid & 31;
    const int warp = tid >> 5;
    const int wm = (warp & 3) * 32;   // warp M offset
    const int wn = (warp >> 2) * 32;  // warp N offset

    float acc[2][4][4];
#pragma unroll
    for (int i = 0; i < 2; i++)
#pragma unroll
        for (int j = 0; j < 4; j++)
#pragma unroll
            for (int q = 0; q < 4; q++) acc[i][j][q] = 0.0f;

    // Global load coords: each thread owns one row, two float4 columns.
    const int lrow = tid >> 2;            // 0..127
    const int lc4  = (tid & 3) * 2;       // float4 col {0,2,4,6} (+1)

    // ldmatrix lane-dependent offsets (within a tile)
    const uint32_t aoff = (uint32_t)((wm + (lane & 15)) * SM_LDR + (lane >> 4) * 16);
    const uint32_t boff = (uint32_t)((wn + (lane & 7) + ((lane >> 4) & 1) * 8) * SM_LDR
                                     + ((lane >> 3) & 1) * 16);

    // Prefetch kt=0 and fill stage 0
    float4 pa0 = *(const float4*)(A  + (size_t)(m0 + lrow) * K + lc4 * 4);
    float4 pa1 = *(const float4*)(A  + (size_t)(m0 + lrow) * K + (lc4 + 1) * 4);
    float4 pb0 = *(const float4*)(Bm + (size_t)(n0 + lrow) * K + lc4 * 4);
    float4 pb1 = *(const float4*)(Bm + (size_t)(n0 + lrow) * K + (lc4 + 1) * 4);
    cvt_store(dsm + 0 * TILE_B, dsm + 1 * TILE_B, lrow, lc4,     pa0);
    cvt_store(dsm + 0 * TILE_B, dsm + 1 * TILE_B, lrow, lc4 + 1, pa1);
    cvt_store(dsm + 2 * TILE_B, dsm + 3 * TILE_B, lrow, lc4,     pb0);
    cvt_store(dsm + 2 * TILE_B, dsm + 3 * TILE_B, lrow, lc4 + 1, pb1);
    __syncthreads();

    for (int kt = 0; kt < K; kt += 32) {
        const int cur = (kt >> 5) & 1;
        const int nxt = cur ^ 1;
        const bool more = (kt + 32 < K);

        // Issue next tile's global loads first (latency hidden by MMAs below)
        if (more) {
            pa0 = *(const float4*)(A  + (size_t)(m0 + lrow) * K + kt + 32 + lc4 * 4);
            pa1 = *(const float4*)(A  + (size_t)(m0 + lrow) * K + kt + 32 + (lc4 + 1) * 4);
            pb0 = *(const float4*)(Bm + (size_t)(n0 + lrow) * K + kt + 32 + lc4 * 4);
            pb1 = *(const float4*)(Bm + (size_t)(n0 + lrow) * K + kt + 32 + (lc4 + 1) * 4);
        }

        const uint32_t aHi = smBase + (uint32_t)(cur * 4 + 0) * TILE_B;
        const uint32_t aLo = smBase + (uint32_t)(cur * 4 + 1) * TILE_B;
        const uint32_t bHi = smBase + (uint32_t)(cur * 4 + 2) * TILE_B;
        const uint32_t bLo = smBase + (uint32_t)(cur * 4 + 3) * TILE_B;

#pragma unroll
        for (int k16 = 0; k16 < 2; k16++) {
            uint32_t ah[2][4], al[2][4], bh[4][2], bl[4][2];
#pragma unroll
            for (int mi = 0; mi < 2; mi++) {
                uint32_t d = aoff + mi * (16 * SM_LDR) + k16 * 32;
                LDMX4(ah[mi], aHi + d);
                LDMX4(al[mi], aLo + d);
            }
#pragma unroll
            for (int njp = 0; njp < 2; njp++) {
                uint32_t d = boff + njp * (16 * SM_LDR) + k16 * 32;
                uint32_t th[4], tl[4];
                LDMX4(th, bHi + d);
                LDMX4(tl, bLo + d);
                bh[2 * njp][0] = th[0]; bh[2 * njp][1] = th[1];
                bh[2 * njp + 1][0] = th[2]; bh[2 * njp + 1][1] = th[3];
                bl[2 * njp][0] = tl[0]; bl[2 * njp][1] = tl[1];
                bl[2 * njp + 1][0] = tl[2]; bl[2 * njp + 1][1] = tl[3];
            }
#pragma unroll
            for (int mi = 0; mi < 2; mi++)
#pragma unroll
                for (int nj = 0; nj < 4; nj++) {
                    MMA16816(acc[mi][nj], ah[mi], bh[nj]);
                    MMA16816(acc[mi][nj], ah[mi], bl[nj]);
                    MMA16816(acc[mi][nj], al[mi], bh[nj]);
                }
        }

        // Convert next tile into the other stage while MMAs drain
        if (more) {
            char* pAh = dsm + (nxt * 4 + 0) * TILE_B;
            char* pAl = dsm + (nxt * 4 + 1) * TILE_B;
            char* pBh = dsm + (nxt * 4 + 2) * TILE_B;
            char* pBl = dsm + (nxt * 4 + 3) * TILE_B;
            cvt_store(pAh, pAl, lrow, lc4,     pa0);
            cvt_store(pAh, pAl, lrow, lc4 + 1, pa1);
            cvt_store(pBh, pBl, lrow, lc4,     pb0);
            cvt_store(pBh, pBl, lrow, lc4 + 1, pb1);
        }
        __syncthreads();
    }

    // Epilogue: frag (c0,c1)=row er cols ec,ec+1; (c2,c3)=row er+8
    const int er = lane >> 2;
    const int ec = (lane & 3) * 2;
#pragma unroll
    for (int nj = 0; nj < 4; nj++) {
        int n = n0 + wn + nj * 8 + ec;
        float bb0 = b1[n]     + (b2 ? b2[n]     : 0.0f);
        float bb1 = b1[n + 1] + (b2 ? b2[n + 1] : 0.0f);
#pragma unroll
        for (int mi = 0; mi < 2; mi++) {
            int r0 = m0 + wm + mi * 16 + er;
            float v0 = acc[mi][nj][0] + bb0;
            float v1 = acc[mi][nj][1] + bb1;
            float v2 = acc[mi][nj][2] + bb0;
            float v3 = acc[mi][nj][3] + bb1;
            if (SIG) { v0 = sigm(v0); v1 = sigm(v1); v2 = sigm(v2); v3 = sigm(v3); }
            *(float2*)(C + (size_t)r0 * CLD + n)       = make_float2(v0, v1);
            *(float2*)(C + (size_t)(r0 + 8) * CLD + n) = make_float2(v2, v3);
        }
    }
}

#define GEMM_SMEM_BYTES (8 * TILE_B)   // 81920

// K1: xg = x @ W_ih^T + (b_ih + b_hh)   (M=131072, N=256, K=256)
__global__ void __launch_bounds__(512, 1)
k_xg_mma(const float* __restrict__ x, const float* __restrict__ Wih,
         const float* __restrict__ bih, const float* __restrict__ bhh) {
    gemm_mma_body<INPUT_, GATES_, false>(x, Wih, bih, bhh, g_xg,
                                         blockIdx.y * 128, blockIdx.x * 128);
}

// K3: out = sigmoid(hs @ W_out^T + b_out)   (M=131072, N=1024, K=64)
__global__ void __launch_bounds__(512, 1)
k_out_mma(const float* __restrict__ Wout, const float* __restrict__ bout,
          float* __restrict__ out) {
    gemm_mma_body<HID_, OUT_, true>(g_hs, Wout, bout, nullptr, out,
                                    blockIdx.y * 128, blockIdx.x * 128);
}

// ---------------- K2: LSTM recurrence ----------------
// One CTA per batch element; thread tid owns gate row tid of W_hh.
// 4-deep xg prefetch, 4 FMA2 chains, tanh.approx, 2 CTAs/SM (1 wave).
__global__ void __launch_bounds__(256, 2)
k_lstm(const float* __restrict__ h0, const float* __restrict__ c0,
       const float* __restrict__ Whh,
       float* __restrict__ hT, float* __restrict__ cT) {
    const int b = blockIdx.x;
    const int tid = threadIdx.x;

    unsigned long long w2[32];
    const float4* wr = (const float4*)(Whh + tid * HID_);
#pragma unroll
    for (int q = 0; q < 16; q++) {
        float4 v = wr[q];
        w2[2 * q]     = pk(v.x, v.y);
        w2[2 * q + 1] = pk(v.z, v.w);
    }

    __shared__ __align__(16) float hsh[HID_];
    __shared__ float act[GATES_];

    float c = 0.0f;
    if (tid < HID_) {
        hsh[tid] = h0[b * HID_ + tid];
        c = c0[b * HID_ + tid];
    }
    __syncthreads();

    const float* xp = g_xg + (size_t)b * GATES_ + tid;  // step stride BATCH*GATES_

#define XLD(tq) (((tq) < T_STEPS) ? xp[(size_t)(tq) * (BATCH * GATES_)] : 0.0f)

#define LSTM_STEP(XV, T)                                                        \
    do {                                                                        \
        unsigned long long a0 = 0, a1 = 0, a2 = 0, a3 = 0;                      \
        const ulonglong2* hp = (const ulonglong2*)hsh;                          \
        _Pragma("unroll")                                                       \
        for (int q = 0; q < 8; q++) {                                           \
            ulonglong2 hA = hp[2 * q], hB = hp[2 * q + 1];                      \
            fma2(a0, w2[4 * q],     hA.x);                                      \
            fma2(a1, w2[4 * q + 1], hA.y);                                      \
            fma2(a2, w2[4 * q + 2], hB.x);                                      \
            fma2(a3, w2[4 * q + 3], hB.y);                                      \
        }                                                                       \
        float2 s0 = upk(a0), s1 = upk(a1), s2 = upk(a2), s3 = upk(a3);          \
        float s = (XV) + (((s0.x + s0.y) + (s1.x + s1.y)) +                     \
                          ((s2.x + s2.y) + (s3.x + s3.y)));                     \
        float a = (tid >= 128 && tid < 192) ? tanh_fast(s) : sigm(s);           \
        act[tid] = a;                                                           \
        __syncthreads();                                                        \
        if (tid < HID_) {                                                       \
            float i_ = act[tid];                                                \
            float f_ = act[HID_ + tid];                                         \
            float g_ = act[2 * HID_ + tid];                                     \
            float o_ = act[3 * HID_ + tid];                                     \
            c = f_ * c + i_ * g_;                                               \
            float h = o_ * tanh_fast(c);                                        \
            hsh[tid] = h;                                                       \
            g_hs[((size_t)(T) * BATCH + b) * HID_ + tid] = h;                   \
        }                                                                       \
        __syncthreads();                                                        \
    } while (0)

    float x0 = XLD(0), x1 = XLD(1), x2 = XLD(2), x3 = XLD(3);
    for (int t = 0; t < T_STEPS; t += 4) {
        float n0_ = XLD(t + 4), n1_ = XLD(t + 5), n2_ = XLD(t + 6), n3_ = XLD(t + 7);
        LSTM_STEP(x0, t);
        LSTM_STEP(x1, t + 1);
        LSTM_STEP(x2, t + 2);
        LSTM_STEP(x3, t + 3);
        x0 = n0_; x1 = n1_; x2 = n2_; x3 = n3_;
    }

    if (tid < HID_) {
        hT[b * HID_ + tid] = hsh[tid];
        cT[b * HID_ + tid] = c;
    }
#undef LSTM_STEP
#undef XLD
}

extern "C" void kernel_launch(void* const* d_in, const int* in_sizes, int n_in,
                              void* d_out, int out_size) {
    const float* x    = (const float*)d_in[0];
    const float* h0   = (const float*)d_in[1];
    const float* c0   = (const float*)d_in[2];
    const float* Wih  = (const float*)d_in[3];
    const float* Whh  = (const float*)d_in[4];
    const float* bih  = (const float*)d_in[5];
    const float* bhh  = (const float*)d_in[6];
    const float* Wout = (const float*)d_in[7];
    const float* bout = (const float*)d_in[8];

    float* out = (float*)d_out;
    float* hT  = out + OUT_ELEMS;
    float* cT  = hT + HC_ELEMS;

    static int cfg_done = 0;
    if (!cfg_done) {
        cudaFuncSetAttribute(k_xg_mma, cudaFuncAttributeMaxDynamicSharedMemorySize,
                             GEMM_SMEM_BYTES);
        cudaFuncSetAttribute(k_out_mma, cudaFuncAttributeMaxDynamicSharedMemorySize,
                             GEMM_SMEM_BYTES);
        cfg_done = 1;
    }

    // 1) xg = x @ W_ih^T + (b_ih + b_hh)   — bf16 split-2 tensor cores, 2-stage pipe
    k_xg_mma<<<dim3(GATES_ / 128, M_ROWS / 128), 512, GEMM_SMEM_BYTES>>>(x, Wih, bih, bhh);
    // 2) sequential LSTM recurrence (1 wave: 2 CTAs/SM)
    k_lstm<<<BATCH, 256>>>(h0, c0, Whh, hT, cT);
    // 3) out = sigmoid(hs @ W_out^T + b_out) — bf16 split-2 tensor cores
    k_out_mma<<<dim3(OUT_ / 128, M_ROWS / 128), 512, GEMM_SMEM_BYTES>>>(Wout, bout, out);
}

// round 14
// speedup vs baseline: 1.9805x; 1.0660x over previous
#include <cuda_runtime.h>
#include <cuda_bf16.h>
#include <cstdint>

// ---------------- Problem constants ----------------
#define T_STEPS 512
#define BATCH   256
#define INPUT_  256
#define HID_    64
#define GATES_  256            // 4*HID
#define OUT_    1024
#define M_ROWS  (T_STEPS * BATCH)          // 131072
#define OUT_ELEMS ((size_t)M_ROWS * OUT_)
#define HC_ELEMS  (BATCH * HID_)

// Scratch (allocation-free rule: __device__ globals)
__device__ float g_xg[(size_t)M_ROWS * GATES_];            // gate pre-activations (fp32)
__device__ __nv_bfloat16 g_x_hi[(size_t)M_ROWS * INPUT_];  // x split-2 bf16
__device__ __nv_bfloat16 g_x_lo[(size_t)M_ROWS * INPUT_];
__device__ __nv_bfloat16 g_hs_hi[(size_t)M_ROWS * HID_];   // hidden states split-2
__device__ __nv_bfloat16 g_hs_lo[(size_t)M_ROWS * HID_];
__device__ __nv_bfloat16 g_wih_hi[GATES_ * INPUT_];
__device__ __nv_bfloat16 g_wih_lo[GATES_ * INPUT_];
__device__ __nv_bfloat16 g_wout_hi[OUT_ * HID_];
__device__ __nv_bfloat16 g_wout_lo[OUT_ * HID_];

// ---------------- helpers ----------------
__device__ __forceinline__ uint32_t smem_u32(const void* p) {
    uint32_t a;
    asm("{ .reg .u64 t; cvta.to.shared.u64 t, %1; cvt.u32.u64 %0, t; }"
        : "=r"(a) : "l"(p));
    return a;
}
__device__ __forceinline__ float tanh_fast(float x) {
    float y;
    asm("tanh.approx.f32 %0, %1;" : "=f"(y) : "f"(x));
    return y;
}
__device__ __forceinline__ float sigm(float x) {      // 1 MUFU-class op
    return 0.5f * tanh_fast(0.5f * x) + 0.5f;
}

// Plain-target tensor / async-copy PTX (sm_80+ features only).
#define LDMX4(r, addr) \
    asm volatile("ldmatrix.sync.aligned.m8n8.x4.shared.b16 {%0,%1,%2,%3}, [%4];" \
        : "=r"((r)[0]), "=r"((r)[1]), "=r"((r)[2]), "=r"((r)[3]) : "r"(addr))

#define MMA16816(d, a, b) \
    asm volatile("mma.sync.aligned.m16n8k16.row.col.f32.bf16.bf16.f32 " \
        "{%0,%1,%2,%3}, {%4,%5,%6,%7}, {%8,%9}, {%0,%1,%2,%3};" \
        : "+f"((d)[0]), "+f"((d)[1]), "+f"((d)[2]), "+f"((d)[3]) \
        : "r"((a)[0]), "r"((a)[1]), "r"((a)[2]), "r"((a)[3]), \
          "r"((b)[0]), "r"((b)[1]))

#define CPA16(dst, src) \
    asm volatile("cp.async.cg.shared.global [%0], [%1], 16;" \
                 :: "r"(dst), "l"(src) : "memory")
#define CPA_COMMIT() asm volatile("cp.async.commit_group;" ::: "memory")
#define CPA_WAIT0()  asm volatile("cp.async.wait_group 0;" ::: "memory")
#define CPA_WAIT1()  asm volatile("cp.async.wait_group 1;" ::: "memory")

// ---------------- f32x2 packed-FMA helpers (LSTM) ----------------
__device__ __forceinline__ unsigned long long pk(float x, float y) {
    unsigned long long r;
    asm("mov.b64 %0, {%1, %2};" : "=l"(r) : "f"(x), "f"(y));
    return r;
}
__device__ __forceinline__ void fma2(unsigned long long& d,
                                     unsigned long long a, unsigned long long b) {
    asm("fma.rn.f32x2 %0, %1, %2, %0;" : "+l"(d) : "l"(a), "l"(b));
}
__device__ __forceinline__ float2 upk(unsigned long long v) {
    float2 r;
    asm("mov.b64 {%0, %1}, %2;" : "=f"(r.x), "=f"(r.y) : "l"(v));
    return r;
}

// ---------------- split-2 pre-conversion kernels ----------------
__device__ __forceinline__ uint32_t bfh(float2 v) {
    __nv_bfloat162 h = __float22bfloat162_rn(v);
    return *(uint32_t*)&h;
}
__global__ void __launch_bounds__(256)
k_split(const float* __restrict__ src, __nv_bfloat16* __restrict__ hi,
        __nv_bfloat16* __restrict__ lo, int n8) {
    int i = blockIdx.x * 256 + threadIdx.x;
    if (i >= n8) return;
    size_t idx = (size_t)i * 8;
    float4 a = *(const float4*)(src + idx);
    float4 b = *(const float4*)(src + idx + 4);
    float f[8] = {a.x, a.y, a.z, a.w, b.x, b.y, b.z, b.w};
    uint4 hv, lv;
    uint32_t* hp = (uint32_t*)&hv;
    uint32_t* lp = (uint32_t*)&lv;
#pragma unroll
    for (int q = 0; q < 4; q++) {
        float2 p = make_float2(f[2 * q], f[2 * q + 1]);
        __nv_bfloat162 h = __float22bfloat162_rn(p);
        float2 r = make_float2(p.x - __bfloat162float(h.x),
                               p.y - __bfloat162float(h.y));
        hp[q] = *(uint32_t*)&h;
        lp[q] = bfh(r);
    }
    *(uint4*)(hi + idx) = hv;
    *(uint4*)(lo + idx) = lv;
}

// ---------------- mma.sync GEMM (bf16 pre-split, cp.async pipeline) --------
// C[m][n] = act( A[m][K] . B[n][K]^T + bias ), CTA tile 128x128, BK=32.
// Split-2: D = Ahi*Bhi + Ahi*Blo + Alo*Bhi (fp32 accum).
// 8 warps as 2(M) x 4(N); warp tile 64x32 = 4x4 m16n8k16 tiles.
// Smem: 2 stages x 4 tiles x (128 rows x 80B) = 80 KB dynamic; 2 CTAs/SM.
#define SM_LDR 80
#define TILE_B (128 * SM_LDR)
#define GEMM_SMEM_BYTES (8 * TILE_B)   // 81920

template <int K>
__device__ __forceinline__ void issue_tile(
    uint32_t smStage,
    const __nv_bfloat16* __restrict__ Ahi, const __nv_bfloat16* __restrict__ Alo,
    const __nv_bfloat16* __restrict__ Bhi, const __nv_bfloat16* __restrict__ Blo,
    int m0, int n0, int kt, int lrow, int lc16) {
    const size_t arow = (size_t)(m0 + lrow) * K + kt;
    const size_t brow = (size_t)(n0 + lrow) * K + kt;
#pragma unroll
    for (int c = 0; c < 2; c++) {
        uint32_t d = smStage + (uint32_t)(lrow * SM_LDR + (lc16 + c) * 16);
        int e = (lc16 + c) * 8;
        CPA16(d,              Ahi + arow + e);
        CPA16(d + TILE_B,     Alo + arow + e);
        CPA16(d + 2 * TILE_B, Bhi + brow + e);
        CPA16(d + 3 * TILE_B, Blo + brow + e);
    }
}

template <int K, int CLD, bool SIG>
__device__ __forceinline__ void gemm_body(
    const __nv_bfloat16* __restrict__ Ahi, const __nv_bfloat16* __restrict__ Alo,
    const __nv_bfloat16* __restrict__ Bhi, const __nv_bfloat16* __restrict__ Blo,
    const float* __restrict__ b1, const float* __restrict__ b2,
    float* __restrict__ C, int m0, int n0) {
    extern __shared__ char dsm[];
    const uint32_t smBase = smem_u32(dsm);

    const int tid  = threadIdx.x;
    const int lane = tid & 31;
    const int warp = tid >> 5;
    const int wm = (warp & 1) * 64;    // warp M offset (64 rows)
    const int wn = (warp >> 1) * 32;   // warp N offset (32 cols)

    float acc[4][4][4];
#pragma unroll
    for (int i = 0; i < 4; i++)
#pragma unroll
        for (int j = 0; j < 4; j++)
#pragma unroll
            for (int q = 0; q < 4; q++) acc[i][j][q] = 0.0f;

    // cp.async coords: each thread owns one row half (two 16B chunks per tile)
    const int lrow = tid >> 1;         // 0..127
    const int lc16 = (tid & 1) * 2;    // chunk {0,1} or {2,3}

    // ldmatrix per-lane offsets (within one 128x80B tile)
    const uint32_t aoff = (uint32_t)((wm + (lane & 15)) * SM_LDR + (lane >> 4) * 16);
    const uint32_t boff = (uint32_t)((wn + (lane & 7) + ((lane >> 4) & 1) * 8) * SM_LDR
                                     + ((lane >> 3) & 1) * 16);

    issue_tile<K>(smBase, Ahi, Alo, Bhi, Blo, m0, n0, 0, lrow, lc16);
    CPA_COMMIT();

    int cur = 0;
    for (int kt = 0; kt < K; kt += 32, cur ^= 1) {
        const bool more = (kt + 32 < K);
        if (more) {
            issue_tile<K>(smBase + (cur ^ 1) * (4 * TILE_B),
                          Ahi, Alo, Bhi, Blo, m0, n0, kt + 32, lrow, lc16);
            CPA_COMMIT();
            CPA_WAIT1();
        } else {
            CPA_WAIT0();
        }
        __syncthreads();

        const uint32_t tb  = smBase + cur * (4 * TILE_B);
        const uint32_t aHi = tb, aLo = tb + TILE_B;
        const uint32_t bHi = tb + 2 * TILE_B, bLo = tb + 3 * TILE_B;

#pragma unroll
        for (int k16 = 0; k16 < 2; k16++) {
            uint32_t bh[4][2], bl[4][2];
#pragma unroll
            for (int njp = 0; njp < 2; njp++) {
                uint32_t th[4], tl[4];
                uint32_t d = boff + njp * (16 * SM_LDR) + k16 * 32;
                LDMX4(th, bHi + d);
                LDMX4(tl, bLo + d);
                bh[2 * njp][0] = th[0]; bh[2 * njp][1] = th[1];
                bh[2 * njp + 1][0] = th[2]; bh[2 * njp + 1][1] = th[3];
                bl[2 * njp][0] = tl[0]; bl[2 * njp][1] = tl[1];
                bl[2 * njp + 1][0] = tl[2]; bl[2 * njp + 1][1] = tl[3];
            }
#pragma unroll
            for (int mi = 0; mi < 4; mi++) {
                uint32_t ah[4], al[4];
                uint32_t d = aoff + mi * (16 * SM_LDR) + k16 * 32;
                LDMX4(ah, aHi + d);
                LDMX4(al, aLo + d);
#pragma unroll
                for (int nj = 0; nj < 4; nj++) {
                    MMA16816(acc[mi][nj], ah, bh[nj]);
                    MMA16816(acc[mi][nj], ah, bl[nj]);
                    MMA16816(acc[mi][nj], al, bh[nj]);
                }
            }
        }
        __syncthreads();
    }

    // Epilogue: frag (c0,c1)=row er cols ec,ec+1; (c2,c3)=row er+8
    const int er = lane >> 2;
    const int ec = (lane & 3) * 2;
#pragma unroll
    for (int nj = 0; nj < 4; nj++) {
        int n = n0 + wn + nj * 8 + ec;
        float bb0 = b1[n]     + (b2 ? b2[n]     : 0.0f);
        float bb1 = b1[n + 1] + (b2 ? b2[n + 1] : 0.0f);
#pragma unroll
        for (int mi = 0; mi < 4; mi++) {
            int r0 = m0 + wm + mi * 16 + er;
            float v0 = acc[mi][nj][0] + bb0;
            float v1 = acc[mi][nj][1] + bb1;
            float v2 = acc[mi][nj][2] + bb0;
            float v3 = acc[mi][nj][3] + bb1;
            if (SIG) { v0 = sigm(v0); v1 = sigm(v1); v2 = sigm(v2); v3 = sigm(v3); }
            *(float2*)(C + (size_t)r0 * CLD + n)       = make_float2(v0, v1);
            *(float2*)(C + (size_t)(r0 + 8) * CLD + n) = make_float2(v2, v3);
        }
    }
}

// K1: xg = x @ W_ih^T + (b_ih + b_hh)   (M=131072, N=256, K=256)
__global__ void __launch_bounds__(256, 2)
k_xg_mma(const float* __restrict__ bih, const float* __restrict__ bhh) {
    gemm_body<INPUT_, GATES_, false>(g_x_hi, g_x_lo, g_wih_hi, g_wih_lo,
                                     bih, bhh, g_xg,
                                     blockIdx.y * 128, blockIdx.x * 128);
}

// K3: out = sigmoid(hs @ W_out^T + b_out)   (M=131072, N=1024, K=64)
__global__ void __launch_bounds__(256, 2)
k_out_mma(const float* __restrict__ bout, float* __restrict__ out) {
    gemm_body<HID_, OUT_, true>(g_hs_hi, g_hs_lo, g_wout_hi, g_wout_lo,
                                bout, nullptr, out,
                                blockIdx.y * 128, blockIdx.x * 128);
}

// ---------------- K2: LSTM recurrence ----------------
// One CTA per batch element; thread tid owns gate row tid of W_hh.
// 4-deep xg prefetch, 4 FMA2 chains, tanh.approx, 2 CTAs/SM.
// Writes hs as split-2 bf16 (consumed directly by k_out_mma).
__global__ void __launch_bounds__(256, 2)
k_lstm(const float* __restrict__ h0, const float* __restrict__ c0,
       const float* __restrict__ Whh,
       float* __restrict__ hT, float* __restrict__ cT) {
    const int b = blockIdx.x;
    const int tid = threadIdx.x;

    unsigned long long w2[32];
    const float4* wr = (const float4*)(Whh + tid * HID_);
#pragma unroll
    for (int q = 0; q < 16; q++) {
        float4 v = wr[q];
        w2[2 * q]     = pk(v.x, v.y);
        w2[2 * q + 1] = pk(v.z, v.w);
    }

    __shared__ __align__(16) float hsh[HID_];
    __shared__ float act[GATES_];

    float c = 0.0f;
    if (tid < HID_) {
        hsh[tid] = h0[b * HID_ + tid];
        c = c0[b * HID_ + tid];
    }
    __syncthreads();

    const float* xp = g_xg + (size_t)b * GATES_ + tid;  // step stride BATCH*GATES_

#define XLD(tq) (((tq) < T_STEPS) ? xp[(size_t)(tq) * (BATCH * GATES_)] : 0.0f)

#define LSTM_STEP(XV, T)                                                        \
    do {                                                                        \
        unsigned long long a0 = 0, a1 = 0, a2 = 0, a3 = 0;                      \
        const ulonglong2* hp = (const ulonglong2*)hsh;                          \
        _Pragma("unroll")                                                       \
        for (int q = 0; q < 8; q++) {                                           \
            ulonglong2 hA = hp[2 * q], hB = hp[2 * q + 1];                      \
            fma2(a0, w2[4 * q],     hA.x);                                      \
            fma2(a1, w2[4 * q + 1], hA.y);                                      \
            fma2(a2, w2[4 * q + 2], hB.x);                                      \
            fma2(a3, w2[4 * q + 3], hB.y);                                      \
        }                                                                       \
        float2 s0 = upk(a0), s1 = upk(a1), s2 = upk(a2), s3 = upk(a3);          \
        float s = (XV) + (((s0.x + s0.y) + (s1.x + s1.y)) +                     \
                          ((s2.x + s2.y) + (s3.x + s3.y)));                     \
        float a = (tid >= 128 && tid < 192) ? tanh_fast(s) : sigm(s);           \
        act[tid] = a;                                                           \
        __syncthreads();                                                        \
        if (tid < HID_) {                                                       \
            float i_ = act[tid];                                                \
            float f_ = act[HID_ + tid];                                         \
            float g_ = act[2 * HID_ + tid];                                     \
            float o_ = act[3 * HID_ + tid];                                     \
            c = f_ * c + i_ * g_;                                               \
            float h = o_ * tanh_fast(c);                                        \
            hsh[tid] = h;                                                       \
            size_t off = ((size_t)(T) * BATCH + b) * HID_ + tid;                \
            __nv_bfloat16 hh = __float2bfloat16(h);                             \
            g_hs_hi[off] = hh;                                                  \
            g_hs_lo[off] = __float2bfloat16(h - __bfloat162float(hh));          \
        }                                                                       \
        __syncthreads();                                                        \
    } while (0)

    float x0 = XLD(0), x1 = XLD(1), x2 = XLD(2), x3 = XLD(3);
    for (int t = 0; t < T_STEPS; t += 4) {
        float n0_ = XLD(t + 4), n1_ = XLD(t + 5), n2_ = XLD(t + 6), n3_ = XLD(t + 7);
        LSTM_STEP(x0, t);
        LSTM_STEP(x1, t + 1);
        LSTM_STEP(x2, t + 2);
        LSTM_STEP(x3, t + 3);
        x0 = n0_; x1 = n1_; x2 = n2_; x3 = n3_;
    }

    if (tid < HID_) {
        hT[b * HID_ + tid] = hsh[tid];
        cT[b * HID_ + tid] = c;
    }
#undef LSTM_STEP
#undef XLD
}

extern "C" void kernel_launch(void* const* d_in, const int* in_sizes, int n_in,
                              void* d_out, int out_size) {
    const float* x    = (const float*)d_in[0];
    const float* h0   = (const float*)d_in[1];
    const float* c0   = (const float*)d_in[2];
    const float* Wih  = (const float*)d_in[3];
    const float* Whh  = (const float*)d_in[4];
    const float* bih  = (const float*)d_in[5];
    const float* bhh  = (const float*)d_in[6];
    const float* Wout = (const float*)d_in[7];
    const float* bout = (const float*)d_in[8];

    float* out = (float*)d_out;
    float* hT  = out + OUT_ELEMS;
    float* cT  = hT + HC_ELEMS;

    cudaFuncSetAttribute(k_xg_mma, cudaFuncAttributeMaxDynamicSharedMemorySize,
                         GEMM_SMEM_BYTES);
    cudaFuncSetAttribute(k_out_mma, cudaFuncAttributeMaxDynamicSharedMemorySize,
                         GEMM_SMEM_BYTES);
    cudaFuncSetAttribute(k_xg_mma, cudaFuncAttributePreferredSharedMemoryCarveout, 100);
    cudaFuncSetAttribute(k_out_mma, cudaFuncAttributePreferredSharedMemoryCarveout, 100);

    __nv_bfloat16 *xh, *xl, *wih_h, *wih_l, *wout_h, *wout_l;
    cudaGetSymbolAddress((void**)&xh, g_x_hi);
    cudaGetSymbolAddress((void**)&xl, g_x_lo);
    cudaGetSymbolAddress((void**)&wih_h, g_wih_hi);
    cudaGetSymbolAddress((void**)&wih_l, g_wih_lo);
    cudaGetSymbolAddress((void**)&wout_h, g_wout_hi);
    cudaGetSymbolAddress((void**)&wout_l, g_wout_lo);

    // 0) split-2 bf16 pre-conversion (x and weights)
    k_split<<<(M_ROWS * INPUT_ / 8 + 255) / 256, 256>>>(x, xh, xl, M_ROWS * INPUT_ / 8);
    k_split<<<(GATES_ * INPUT_ / 8 + 255) / 256, 256>>>(Wih, wih_h, wih_l, GATES_ * INPUT_ / 8);
    k_split<<<(OUT_ * HID_ / 8 + 255) / 256, 256>>>(Wout, wout_h, wout_l, OUT_ * HID_ / 8);

    // 1) xg = x @ W_ih^T + (b_ih + b_hh)
    k_xg_mma<<<dim3(GATES_ / 128, M_ROWS / 128), 256, GEMM_SMEM_BYTES>>>(bih, bhh);
    // 2) sequential LSTM recurrence
    k_lstm<<<BATCH, 256>>>(h0, c0, Whh, hT, cT);
    // 3) out = sigmoid(hs @ W_out^T + b_out)
    k_out_mma<<<dim3(OUT_ / 128, M_ROWS / 128), 256, GEMM_SMEM_BYTES>>>(bout, out);
}

// round 15
// speedup vs baseline: 2.6913x; 1.3589x over previous
#include <cuda_runtime.h>
#include <cuda_fp16.h>
#include <cstdint>

// ---------------- Problem constants ----------------
#define T_STEPS 512
#define BATCH   256
#define INPUT_  256
#define HID_    64
#define GATES_  256            // 4*HID
#define OUT_    1024
#define M_ROWS  (T_STEPS * BATCH)          // 131072
#define OUT_ELEMS ((size_t)M_ROWS * OUT_)
#define HC_ELEMS  (BATCH * HID_)

// Scratch (allocation-free rule: __device__ globals)
__device__ float  g_xg[(size_t)M_ROWS * GATES_];    // gate pre-activations (fp32)
__device__ __half g_x_h[(size_t)M_ROWS * INPUT_];   // x as fp16
__device__ __half g_hs_h[(size_t)M_ROWS * HID_];    // hidden states as fp16
__device__ __half g_wih_hi[GATES_ * INPUT_];        // W_ih split-2 fp16
__device__ __half g_wih_lo[GATES_ * INPUT_];
__device__ __half g_wout_h[OUT_ * HID_];            // W_out fp16 (single)

// ---------------- helpers ----------------
__device__ __forceinline__ uint32_t smem_u32(const void* p) {
    uint32_t a;
    asm("{ .reg .u64 t; cvta.to.shared.u64 t, %1; cvt.u32.u64 %0, t; }"
        : "=r"(a) : "l"(p));
    return a;
}
__device__ __forceinline__ float tanh_fast(float x) {
    float y;
    asm("tanh.approx.f32 %0, %1;" : "=f"(y) : "f"(x));
    return y;
}
__device__ __forceinline__ float sigm(float x) {      // 1 MUFU-class op
    return 0.5f * tanh_fast(0.5f * x) + 0.5f;
}

// Plain-target tensor / async-copy PTX (sm_80+ features only).
#define LDMX4(r, addr) \
    asm volatile("ldmatrix.sync.aligned.m8n8.x4.shared.b16 {%0,%1,%2,%3}, [%4];" \
        : "=r"((r)[0]), "=r"((r)[1]), "=r"((r)[2]), "=r"((r)[3]) : "r"(addr))

#define MMA16816(d, a, b) \
    asm volatile("mma.sync.aligned.m16n8k16.row.col.f32.f16.f16.f32 " \
        "{%0,%1,%2,%3}, {%4,%5,%6,%7}, {%8,%9}, {%0,%1,%2,%3};" \
        : "+f"((d)[0]), "+f"((d)[1]), "+f"((d)[2]), "+f"((d)[3]) \
        : "r"((a)[0]), "r"((a)[1]), "r"((a)[2]), "r"((a)[3]), \
          "r"((b)[0]), "r"((b)[1]))

#define CPA16(dst, src) \
    asm volatile("cp.async.cg.shared.global [%0], [%1], 16;" \
                 :: "r"(dst), "l"(src) : "memory")
#define CPA_COMMIT() asm volatile("cp.async.commit_group;" ::: "memory")
#define CPA_WAIT0()  asm volatile("cp.async.wait_group 0;" ::: "memory")
#define CPA_WAIT1()  asm volatile("cp.async.wait_group 1;" ::: "memory")

// ---------------- f32x2 packed-FMA helpers (LSTM) ----------------
__device__ __forceinline__ unsigned long long pk(float x, float y) {
    unsigned long long r;
    asm("mov.b64 %0, {%1, %2};" : "=l"(r) : "f"(x), "f"(y));
    return r;
}
__device__ __forceinline__ void fma2(unsigned long long& d,
                                     unsigned long long a, unsigned long long b) {
    asm("fma.rn.f32x2 %0, %1, %2, %0;" : "+l"(d) : "l"(a), "l"(b));
}
__device__ __forceinline__ float2 upk(unsigned long long v) {
    float2 r;
    asm("mov.b64 {%0, %1}, %2;" : "=f"(r.x), "=f"(r.y) : "l"(v));
    return r;
}

// ---------------- conversion kernels ----------------
// fp32 -> fp16, 8 elems/thread
__global__ void __launch_bounds__(256)
k_cvt_h(const float* __restrict__ src, __half* __restrict__ dst, int n8) {
    int i = blockIdx.x * 256 + threadIdx.x;
    if (i >= n8) return;
    size_t idx = (size_t)i * 8;
    float4 a = *(const float4*)(src + idx);
    float4 b = *(const float4*)(src + idx + 4);
    uint4 o;
    __half2* op = (__half2*)&o;
    op[0] = __floats2half2_rn(a.x, a.y);
    op[1] = __floats2half2_rn(a.z, a.w);
    op[2] = __floats2half2_rn(b.x, b.y);
    op[3] = __floats2half2_rn(b.z, b.w);
    *(uint4*)(dst + idx) = o;
}
// fp32 -> fp16 hi/lo split, 4 elems/thread
__global__ void __launch_bounds__(256)
k_split_h(const float* __restrict__ src, __half* __restrict__ hi,
          __half* __restrict__ lo, int n4) {
    int i = blockIdx.x * 256 + threadIdx.x;
    if (i >= n4) return;
    size_t idx = (size_t)i * 4;
    float4 a = *(const float4*)(src + idx);
    float f[4] = {a.x, a.y, a.z, a.w};
    __half h[4], l[4];
#pragma unroll
    for (int q = 0; q < 4; q++) {
        h[q] = __float2half_rn(f[q]);
        l[q] = __float2half_rn(f[q] - __half2float(h[q]));
    }
    *(uint2*)(hi + idx) = *(uint2*)h;
    *(uint2*)(lo + idx) = *(uint2*)l;
}

// ---------------- mma.sync GEMM (fp16, cp.async, double-buffered) ----------
// C[m][n] = act( A[m][K] . B[n][K]^T + bias ), CTA tile 128x128, BK=32.
// NB=2: D = A*Bhi + A*Blo (split weights).  NB=1: D = A*B.
// 8 warps as 2(M) x 4(N); warp tile 64x32 = 4x4 m16n8k16 tiles.
#define SM_LDR 80
#define TILE_B (128 * SM_LDR)

template <int K, int NB>
__device__ __forceinline__ void issue_tile(
    uint32_t smStage, const __half* __restrict__ A,
    const __half* __restrict__ B0, const __half* __restrict__ B1,
    int m0, int n0, int kt, int lrow, int lc16) {
    const size_t arow = (size_t)(m0 + lrow) * K + kt;
    const size_t brow = (size_t)(n0 + lrow) * K + kt;
#pragma unroll
    for (int c = 0; c < 2; c++) {
        uint32_t d = smStage + (uint32_t)(lrow * SM_LDR + (lc16 + c) * 16);
        int e = (lc16 + c) * 8;
        CPA16(d,          A  + arow + e);
        CPA16(d + TILE_B, B0 + brow + e);
        if (NB == 2) CPA16(d + 2 * TILE_B, B1 + brow + e);
    }
}

template <int K, int CLD, bool SIG, int NB>
__device__ __forceinline__ void gemm_body(
    const __half* __restrict__ A, const __half* __restrict__ B0,
    const __half* __restrict__ B1,
    const float* __restrict__ b1, const float* __restrict__ b2,
    float* __restrict__ C, int m0, int n0) {
    extern __shared__ char dsm[];
    const uint32_t smBase = smem_u32(dsm);
    const uint32_t STAGE_B = (1 + NB) * TILE_B;

    const int tid  = threadIdx.x;
    const int lane = tid & 31;
    const int warp = tid >> 5;
    const int wm = (warp & 1) * 64;    // warp M offset (64 rows)
    const int wn = (warp >> 1) * 32;   // warp N offset (32 cols)

    float acc[4][4][4];
#pragma unroll
    for (int i = 0; i < 4; i++)
#pragma unroll
        for (int j = 0; j < 4; j++)
#pragma unroll
            for (int q = 0; q < 4; q++) acc[i][j][q] = 0.0f;

    const int lrow = tid >> 1;         // 0..127
    const int lc16 = (tid & 1) * 2;    // 16B chunk pair

    const uint32_t aoff = (uint32_t)((wm + (lane & 15)) * SM_LDR + (lane >> 4) * 16);
    const uint32_t boff = (uint32_t)((wn + (lane & 7) + ((lane >> 4) & 1) * 8) * SM_LDR
                                     + ((lane >> 3) & 1) * 16);

    issue_tile<K, NB>(smBase, A, B0, B1, m0, n0, 0, lrow, lc16);
    CPA_COMMIT();

    int cur = 0;
    for (int kt = 0; kt < K; kt += 32, cur ^= 1) {
        const bool more = (kt + 32 < K);
        if (more) {
            issue_tile<K, NB>(smBase + (cur ^ 1) * STAGE_B,
                              A, B0, B1, m0, n0, kt + 32, lrow, lc16);
            CPA_COMMIT();
            CPA_WAIT1();
        } else {
            CPA_WAIT0();
        }
        __syncthreads();

        const uint32_t tb  = smBase + cur * STAGE_B;
        const uint32_t aT  = tb;
        const uint32_t b0T = tb + TILE_B;
        const uint32_t b1T = tb + 2 * TILE_B;

#pragma unroll
        for (int k16 = 0; k16 < 2; k16++) {
            uint32_t bh[4][2], bl[4][2];
#pragma unroll
            for (int njp = 0; njp < 2; njp++) {
                uint32_t th[4];
                uint32_t d = boff + njp * (16 * SM_LDR) + k16 * 32;
                LDMX4(th, b0T + d);
                bh[2 * njp][0] = th[0]; bh[2 * njp][1] = th[1];
                bh[2 * njp + 1][0] = th[2]; bh[2 * njp + 1][1] = th[3];
                if (NB == 2) {
                    uint32_t tl[4];
                    LDMX4(tl, b1T + d);
                    bl[2 * njp][0] = tl[0]; bl[2 * njp][1] = tl[1];
                    bl[2 * njp + 1][0] = tl[2]; bl[2 * njp + 1][1] = tl[3];
                }
            }
#pragma unroll
            for (int mi = 0; mi < 4; mi++) {
                uint32_t ah[4];
                LDMX4(ah, aT + aoff + mi * (16 * SM_LDR) + k16 * 32);
#pragma unroll
                for (int nj = 0; nj < 4; nj++) {
                    MMA16816(acc[mi][nj], ah, bh[nj]);
                    if (NB == 2) MMA16816(acc[mi][nj], ah, bl[nj]);
                }
            }
        }
        __syncthreads();
    }

    // Epilogue: frag (c0,c1)=row er cols ec,ec+1; (c2,c3)=row er+8
    const int er = lane >> 2;
    const int ec = (lane & 3) * 2;
#pragma unroll
    for (int nj = 0; nj < 4; nj++) {
        int n = n0 + wn + nj * 8 + ec;
        float bb0 = b1[n]     + (b2 ? b2[n]     : 0.0f);
        float bb1 = b1[n + 1] + (b2 ? b2[n + 1] : 0.0f);
#pragma unroll
        for (int mi = 0; mi < 4; mi++) {
            int r0 = m0 + wm + mi * 16 + er;
            float v0 = acc[mi][nj][0] + bb0;
            float v1 = acc[mi][nj][1] + bb1;
            float v2 = acc[mi][nj][2] + bb0;
            float v3 = acc[mi][nj][3] + bb1;
            if (SIG) { v0 = sigm(v0); v1 = sigm(v1); v2 = sigm(v2); v3 = sigm(v3); }
            *(float2*)(C + (size_t)r0 * CLD + n)       = make_float2(v0, v1);
            *(float2*)(C + (size_t)(r0 + 8) * CLD + n) = make_float2(v2, v3);
        }
    }
}

#define XG_SMEM  (2 * 3 * TILE_B)   // 61440
#define OUT_SMEM (2 * 2 * TILE_B)   // 40960

// K1: xg = x @ W_ih^T + (b_ih + b_hh) — 2-term fp16 (x single, W split)
__global__ void __launch_bounds__(256, 2)
k_xg_mma(const float* __restrict__ bih, const float* __restrict__ bhh) {
    gemm_body<INPUT_, GATES_, false, 2>(g_x_h, g_wih_hi, g_wih_lo,
                                        bih, bhh, g_xg,
                                        blockIdx.y * 128, blockIdx.x * 128);
}

// K3: out = sigmoid(hs @ W_out^T + b_out) — 1-term fp16 (sigmoid-damped)
__global__ void __launch_bounds__(256, 2)
k_out_mma(const float* __restrict__ bout, float* __restrict__ out) {
    gemm_body<HID_, OUT_, true, 1>(g_hs_h, g_wout_h, nullptr,
                                   bout, nullptr, out,
                                   blockIdx.y * 128, blockIdx.x * 128);
}

// ---------------- K2: LSTM recurrence (1 barrier per step) ----------------
// Warp w owns hids j = 8w..8w+7; lane = gate*8 + jj (gate order i,f,g,o).
// Gate exchange via shfl; h double-buffered in smem; hs written as fp16.
__global__ void __launch_bounds__(256, 2)
k_lstm(const float* __restrict__ h0, const float* __restrict__ c0,
       const float* __restrict__ Whh,
       float* __restrict__ hT, float* __restrict__ cT) {
    const int b    = blockIdx.x;
    const int tid  = threadIdx.x;
    const int lane = tid & 31;
    const int w    = tid >> 5;
    const int gate = lane >> 3;
    const int jj   = lane & 7;
    const int j    = w * 8 + jj;            // hid index this lane tracks
    const int row  = gate * HID_ + j;       // W_hh / xg gate-row

    unsigned long long w2[32];
    const float4* wr = (const float4*)(Whh + row * HID_);
#pragma unroll
    for (int q = 0; q < 16; q++) {
        float4 v = wr[q];
        w2[2 * q]     = pk(v.x, v.y);
        w2[2 * q + 1] = pk(v.z, v.w);
    }

    __shared__ __align__(16) float hb[2][HID_];   // double-buffered h
    if (tid < HID_) hb[0][tid] = h0[b * HID_ + tid];
    float c = c0[b * HID_ + j];   // replicated across the 4 gate groups
    float h = 0.0f;
    __syncthreads();

    const float* xp = g_xg + (size_t)b * GATES_ + row;  // step stride BATCH*GATES_
    int p = 0;

#define XLD(tq) (((tq) < T_STEPS) ? xp[(size_t)(tq) * (BATCH * GATES_)] : 0.0f)

#define LSTM_STEP(XV, T)                                                        \
    do {                                                                        \
        unsigned long long a0 = 0, a1 = 0, a2 = 0, a3 = 0;                      \
        const ulonglong2* hp = (const ulonglong2*)hb[p];                        \
        _Pragma("unroll")                                                       \
        for (int q = 0; q < 8; q++) {                                           \
            ulonglong2 hA = hp[2 * q], hB = hp[2 * q + 1];                      \
            fma2(a0, w2[4 * q],     hA.x);                                      \
            fma2(a1, w2[4 * q + 1], hA.y);                                      \
            fma2(a2, w2[4 * q + 2], hB.x);                                      \
            fma2(a3, w2[4 * q + 3], hB.y);                                      \
        }                                                                       \
        float2 s0 = upk(a0), s1 = upk(a1), s2 = upk(a2), s3 = upk(a3);          \
        float s = (XV) + (((s0.x + s0.y) + (s1.x + s1.y)) +                     \
                          ((s2.x + s2.y) + (s3.x + s3.y)));                     \
        float a_ = (gate == 2) ? tanh_fast(s) : sigm(s);                        \
        float i_ = __shfl_sync(0xffffffffu, a_, jj);                            \
        float f_ = __shfl_sync(0xffffffffu, a_, 8 + jj);                        \
        float g_ = __shfl_sync(0xffffffffu, a_, 16 + jj);                       \
        float o_ = __shfl_sync(0xffffffffu, a_, 24 + jj);                       \
        c = f_ * c + i_ * g_;                                                   \
        h = o_ * tanh_fast(c);                                                  \
        if (gate == 0) {                                                        \
            hb[p ^ 1][j] = h;                                                   \
            g_hs_h[((size_t)(T) * BATCH + b) * HID_ + j] = __float2half(h);     \
        }                                                                       \
        __syncthreads();                                                        \
        p ^= 1;                                                                 \
    } while (0)

    float x0 = XLD(0), x1 = XLD(1), x2 = XLD(2), x3 = XLD(3);
    for (int t = 0; t < T_STEPS; t += 4) {
        float n0_ = XLD(t + 4), n1_ = XLD(t + 5), n2_ = XLD(t + 6), n3_ = XLD(t + 7);
        LSTM_STEP(x0, t);
        LSTM_STEP(x1, t + 1);
        LSTM_STEP(x2, t + 2);
        LSTM_STEP(x3, t + 3);
        x0 = n0_; x1 = n1_; x2 = n2_; x3 = n3_;
    }

    if (gate == 0) {
        hT[b * HID_ + j] = h;
        cT[b * HID_ + j] = c;
    }
#undef LSTM_STEP
#undef XLD
}

extern "C" void kernel_launch(void* const* d_in, const int* in_sizes, int n_in,
                              void* d_out, int out_size) {
    const float* x    = (const float*)d_in[0];
    const float* h0   = (const float*)d_in[1];
    const float* c0   = (const float*)d_in[2];
    const float* Wih  = (const float*)d_in[3];
    const float* Whh  = (const float*)d_in[4];
    const float* bih  = (const float*)d_in[5];
    const float* bhh  = (const float*)d_in[6];
    const float* Wout = (const float*)d_in[7];
    const float* bout = (const float*)d_in[8];

    float* out = (float*)d_out;
    float* hT  = out + OUT_ELEMS;
    float* cT  = hT + HC_ELEMS;

    cudaFuncSetAttribute(k_xg_mma, cudaFuncAttributeMaxDynamicSharedMemorySize, XG_SMEM);
    cudaFuncSetAttribute(k_out_mma, cudaFuncAttributeMaxDynamicSharedMemorySize, OUT_SMEM);

    __half *xh, *wih_h, *wih_l, *wout_h;
    cudaGetSymbolAddress((void**)&xh, g_x_h);
    cudaGetSymbolAddress((void**)&wih_h, g_wih_hi);
    cudaGetSymbolAddress((void**)&wih_l, g_wih_lo);
    cudaGetSymbolAddress((void**)&wout_h, g_wout_h);

    // 0) conversions: x -> fp16; W_ih -> fp16 hi/lo; W_out -> fp16
    k_cvt_h<<<(M_ROWS * INPUT_ / 8 + 255) / 256, 256>>>(x, xh, M_ROWS * INPUT_ / 8);
    k_split_h<<<(GATES_ * INPUT_ / 4 + 255) / 256, 256>>>(Wih, wih_h, wih_l,
                                                          GATES_ * INPUT_ / 4);
    k_cvt_h<<<(OUT_ * HID_ / 8 + 255) / 256, 256>>>(Wout, wout_h, OUT_ * HID_ / 8);

    // 1) xg = x @ W_ih^T + (b_ih + b_hh)
    k_xg_mma<<<dim3(GATES_ / 128, M_ROWS / 128), 256, XG_SMEM>>>(bih, bhh);
    // 2) sequential LSTM recurrence
    k_lstm<<<BATCH, 256>>>(h0, c0, Whh, hT, cT);
    // 3) out = sigmoid(hs @ W_out^T + b_out)
    k_out_mma<<<dim3(OUT_ / 128, M_ROWS / 128), 256, OUT_SMEM>>>(bout, out);
}